// round 2
// baseline (speedup 1.0000x reference)
#include <cuda_runtime.h>
#include <cuda_bf16.h>
#include <cstdint>

// Problem dims (fixed)
#define BB 4
#define TT 2048
#define CC 1024
#define HH 16
#define DD 64
#define FF 4096
#define MM (BB*TT)   // 8192 rows

// ---------------- scratch (device globals; no allocation allowed) ----------
__device__ float g_h [MM*CC];   // LN output (reused for ln1 and ln2)
__device__ float g_q [MM*CC];
__device__ float g_k [MM*CC];
__device__ float g_v [MM*CC];
__device__ float g_at[MM*CC];   // attention output
__device__ float g_x1[MM*CC];   // x + attn@Wo + bo
__device__ float g_ff[MM*FF];   // relu(h2@W1+b1)

// ---------------- LayerNorm: one block per row, 256 threads ----------------
__global__ void __launch_bounds__(256) ln_k(const float* __restrict__ x,
                                            const float* __restrict__ gam,
                                            const float* __restrict__ bet,
                                            float* __restrict__ out)
{
    int row = blockIdx.x;
    int tid = threadIdx.x;
    const float4* xr = (const float4*)(x + (size_t)row * CC);
    float4 v = xr[tid];                       // 256 threads * 4 = 1024 elems
    float s  = v.x + v.y + v.z + v.w;
    float sq = v.x*v.x + v.y*v.y + v.z*v.z + v.w*v.w;
    #pragma unroll
    for (int o = 16; o > 0; o >>= 1) {
        s  += __shfl_xor_sync(0xffffffffu, s,  o);
        sq += __shfl_xor_sync(0xffffffffu, sq, o);
    }
    __shared__ float rs[8], rq[8];
    int w = tid >> 5, lane = tid & 31;
    if (lane == 0) { rs[w] = s; rq[w] = sq; }
    __syncthreads();
    s = 0.f; sq = 0.f;
    #pragma unroll
    for (int i = 0; i < 8; i++) { s += rs[i]; sq += rq[i]; }
    float mu  = s * (1.f / CC);
    float inv = rsqrtf(sq * (1.f / CC) - mu * mu + 1e-5f);
    float4 g4 = ((const float4*)gam)[tid];
    float4 b4 = ((const float4*)bet)[tid];
    float4 r;
    r.x = (v.x - mu) * inv * g4.x + b4.x;
    r.y = (v.y - mu) * inv * g4.y + b4.y;
    r.z = (v.z - mu) * inv * g4.z + b4.z;
    r.w = (v.w - mu) * inv * g4.w + b4.w;
    ((float4*)(out + (size_t)row * CC))[tid] = r;
}

// ---------------- SGEMM: C[M,N] = A[M,K] @ B[K,N] (+epilogue) --------------
// EP: 0 = plain store, 1 = +bias +residual, 2 = relu(+bias)
// 128x128 tile, BK=8, 256 threads, 8x8 per thread (4+4 split),
// double-buffered smem: one __syncthreads per K-tile.
template<int EP>
__global__ void __launch_bounds__(256) sgemm_k(
    const float* __restrict__ A, const float* __restrict__ Bw,
    const float* __restrict__ bias, const float* __restrict__ res,
    float* __restrict__ C, int M, int N, int K)
{
    __shared__ float As[2][8][128];
    __shared__ float Bs[2][8][128];
    int tid = threadIdx.x;
    int bm = blockIdx.y * 128, bn = blockIdx.x * 128;
    int tm = (tid >> 4) * 4;          // 0..60 (rows, +64 for second half)
    int tn = (tid & 15) * 4;          // 0..60 (cols, +64 for second half)
    int arow = tid >> 1, acol = (tid & 1) * 4;
    int brow = tid >> 5, bcol = (tid & 31) * 4;
    const float* Ap = A  + (size_t)(bm + arow) * K + acol;
    const float* Bp = Bw + (size_t)brow * N + bn + bcol;

    float acc[8][8];
    #pragma unroll
    for (int i = 0; i < 8; i++)
        #pragma unroll
        for (int j = 0; j < 8; j++) acc[i][j] = 0.f;

    // preload tile 0 into buffer 0
    float4 av = *(const float4*)Ap;
    float4 bv = *(const float4*)Bp;
    As[0][acol+0][arow] = av.x;
    As[0][acol+1][arow] = av.y;
    As[0][acol+2][arow] = av.z;
    As[0][acol+3][arow] = av.w;
    *(float4*)&Bs[0][brow][bcol] = bv;
    __syncthreads();

    int ktiles = K >> 3;
    int buf = 0;
    for (int t = 0; t < ktiles; t++) {
        // prefetch next tile into registers (overlaps with compute)
        if (t + 1 < ktiles) {
            Ap += 8;
            Bp += (size_t)8 * N;
            av = *(const float4*)Ap;
            bv = *(const float4*)Bp;
        }
        #pragma unroll
        for (int k = 0; k < 8; k++) {
            float4 a0 = *(const float4*)&As[buf][k][tm];
            float4 a1 = *(const float4*)&As[buf][k][tm + 64];
            float4 b0 = *(const float4*)&Bs[buf][k][tn];
            float4 b1 = *(const float4*)&Bs[buf][k][tn + 64];
            float a[8] = {a0.x,a0.y,a0.z,a0.w,a1.x,a1.y,a1.z,a1.w};
            float b[8] = {b0.x,b0.y,b0.z,b0.w,b1.x,b1.y,b1.z,b1.w};
            #pragma unroll
            for (int i = 0; i < 8; i++)
                #pragma unroll
                for (int j = 0; j < 8; j++)
                    acc[i][j] += a[i] * b[j];
        }
        if (t + 1 < ktiles) {
            int nb = buf ^ 1;
            As[nb][acol+0][arow] = av.x;
            As[nb][acol+1][arow] = av.y;
            As[nb][acol+2][arow] = av.z;
            As[nb][acol+3][arow] = av.w;
            *(float4*)&Bs[nb][brow][bcol] = bv;
            __syncthreads();
            buf = nb;
        }
    }

    #pragma unroll
    for (int ii = 0; ii < 2; ii++) {
        #pragma unroll
        for (int i = 0; i < 4; i++) {
            int r = bm + ii * 64 + tm + i;
            size_t base = (size_t)r * N + bn;
            #pragma unroll
            for (int jj = 0; jj < 2; jj++) {
                int c = jj * 64 + tn;
                float4 o;
                o.x = acc[ii*4+i][jj*4+0];
                o.y = acc[ii*4+i][jj*4+1];
                o.z = acc[ii*4+i][jj*4+2];
                o.w = acc[ii*4+i][jj*4+3];
                if (EP == 1 || EP == 2) {
                    float4 bvv = *(const float4*)(bias + bn + c);
                    o.x += bvv.x; o.y += bvv.y; o.z += bvv.z; o.w += bvv.w;
                }
                if (EP == 2) {
                    o.x = fmaxf(o.x, 0.f); o.y = fmaxf(o.y, 0.f);
                    o.z = fmaxf(o.z, 0.f); o.w = fmaxf(o.w, 0.f);
                }
                if (EP == 1) {
                    float4 rv = *(const float4*)(res + base + c);
                    o.x += rv.x; o.y += rv.y; o.z += rv.z; o.w += rv.w;
                }
                *(float4*)(C + base + c) = o;
            }
        }
    }
}

// ---------------- Flash attention (causal, fp32) ---------------------------
// One thread per query row, 128 rows per block, BK=16 key tile, online softmax.
// grid = (T/128, B*H). Scale = C^-0.5 = 1/32 folded into Q at load.
__global__ void __launch_bounds__(128) flash_k(const float* __restrict__ Q,
                                               const float* __restrict__ Kg,
                                               const float* __restrict__ Vg,
                                               float* __restrict__ O)
{
    __shared__ float q_s[128][68];    // [row][d], padded: conflict-free float4
    __shared__ float k_s[16][64];     // [key][d]
    __shared__ float v_s[16][64];     // [key][d]
    int qt  = blockIdx.x;
    int bh  = blockIdx.y;
    int b   = bh >> 4, h = bh & 15;
    int tid = threadIdx.x;

    const float* Qb  = Q  + ((size_t)(b * TT + qt * 128)) * CC + h * DD;
    const float* Kb0 = Kg + ((size_t)b * TT) * CC + h * DD;
    const float* Vb0 = Vg + ((size_t)b * TT) * CC + h * DD;

    // cooperative, coalesced Q tile load (scaled)
    for (int idx = tid; idx < 128 * 16; idx += 128) {
        int r = idx >> 4, d4 = idx & 15;
        float4 t = *(const float4*)(Qb + (size_t)r * CC + d4 * 4);
        t.x *= 0.03125f; t.y *= 0.03125f; t.z *= 0.03125f; t.w *= 0.03125f;
        *(float4*)&q_s[r][d4 * 4] = t;
    }

    int qrow = qt * 128 + tid;
    float m = -1e30f, l = 0.f;
    float o[64];
    #pragma unroll
    for (int d = 0; d < 64; d++) o[d] = 0.f;

    int kend = qt * 128 + 128;           // causal: only keys < (qt+1)*128
    for (int k0 = 0; k0 < kend; k0 += 16) {
        __syncthreads();
        for (int idx = tid; idx < 16 * 16; idx += 128) {
            int r = idx >> 4, d4 = idx & 15;
            *(float4*)&k_s[r][d4*4] = *(const float4*)(Kb0 + (size_t)(k0 + r) * CC + d4 * 4);
            *(float4*)&v_s[r][d4*4] = *(const float4*)(Vb0 + (size_t)(k0 + r) * CC + d4 * 4);
        }
        __syncthreads();

        float s[16];
        #pragma unroll
        for (int j = 0; j < 16; j++) s[j] = 0.f;
        #pragma unroll 4
        for (int d4 = 0; d4 < 16; d4++) {
            float4 q4 = *(const float4*)&q_s[tid][d4 * 4];
            #pragma unroll
            for (int j = 0; j < 16; j++) {
                float4 k4 = *(const float4*)&k_s[j][d4 * 4];
                s[j] += q4.x*k4.x + q4.y*k4.y + q4.z*k4.z + q4.w*k4.w;
            }
        }
        // causal mask within tile
        if (k0 + 15 > qrow) {
            #pragma unroll
            for (int j = 0; j < 16; j++)
                if (k0 + j > qrow) s[j] = -1e30f;
        }
        // online softmax (row-local, no cross-thread reduction)
        float mt = m;
        #pragma unroll
        for (int j = 0; j < 16; j++) mt = fmaxf(mt, s[j]);
        float alpha = __expf(m - mt);
        m = mt;
        l *= alpha;
        #pragma unroll
        for (int d = 0; d < 64; d++) o[d] *= alpha;
        #pragma unroll 4
        for (int j = 0; j < 16; j++) {
            float p = __expf(s[j] - m);
            l += p;
            #pragma unroll
            for (int d4 = 0; d4 < 16; d4++) {
                float4 v4 = *(const float4*)&v_s[j][d4 * 4];
                o[d4*4+0] += p * v4.x;
                o[d4*4+1] += p * v4.y;
                o[d4*4+2] += p * v4.z;
                o[d4*4+3] += p * v4.w;
            }
        }
    }
    float inv = 1.f / l;
    float* Ob = O + ((size_t)(b * TT + qrow)) * CC + h * DD;
    #pragma unroll
    for (int d4 = 0; d4 < 16; d4++) {
        float4 r;
        r.x = o[d4*4+0] * inv;
        r.y = o[d4*4+1] * inv;
        r.z = o[d4*4+2] * inv;
        r.w = o[d4*4+3] * inv;
        *(float4*)(Ob + d4 * 4) = r;
    }
}

// ---------------- launch ----------------------------------------------------
extern "C" void kernel_launch(void* const* d_in, const int* in_sizes, int n_in,
                              void* d_out, int out_size)
{
    const float* x     = (const float*)d_in[0];
    const float* Wq    = (const float*)d_in[1];
    const float* Wk    = (const float*)d_in[2];
    const float* Wv    = (const float*)d_in[3];
    const float* Wo    = (const float*)d_in[4];
    const float* bo    = (const float*)d_in[5];
    const float* W1    = (const float*)d_in[6];
    const float* b1    = (const float*)d_in[7];
    const float* W2    = (const float*)d_in[8];
    const float* b2    = (const float*)d_in[9];
    const float* ln1g  = (const float*)d_in[10];
    const float* ln1b  = (const float*)d_in[11];
    const float* ln2g  = (const float*)d_in[12];
    const float* ln2b  = (const float*)d_in[13];
    float* out = (float*)d_out;

    float *h, *q, *k, *v, *at, *x1, *ff;
    cudaGetSymbolAddress((void**)&h,  g_h);
    cudaGetSymbolAddress((void**)&q,  g_q);
    cudaGetSymbolAddress((void**)&k,  g_k);
    cudaGetSymbolAddress((void**)&v,  g_v);
    cudaGetSymbolAddress((void**)&at, g_at);
    cudaGetSymbolAddress((void**)&x1, g_x1);
    cudaGetSymbolAddress((void**)&ff, g_ff);

    dim3 blk(256);
    dim3 gSmall(CC / 128, MM / 128);   // (8, 64)
    dim3 gFF1(FF / 128, MM / 128);     // (32, 64)

    // 1. h = LN1(x)
    ln_k<<<MM, 256>>>(x, ln1g, ln1b, h);
    // 2. q,k,v = h @ W{q,k,v}
    sgemm_k<0><<<gSmall, blk>>>(h, Wq, nullptr, nullptr, q, MM, CC, CC);
    sgemm_k<0><<<gSmall, blk>>>(h, Wk, nullptr, nullptr, k, MM, CC, CC);
    sgemm_k<0><<<gSmall, blk>>>(h, Wv, nullptr, nullptr, v, MM, CC, CC);
    // 3. attention
    flash_k<<<dim3(TT / 128, BB * HH), 128>>>(q, k, v, at);
    // 4. x1 = x + at @ Wo + bo
    sgemm_k<1><<<gSmall, blk>>>(at, Wo, bo, x, x1, MM, CC, CC);
    // 5. h = LN2(x1)
    ln_k<<<MM, 256>>>(x1, ln2g, ln2b, h);
    // 6. ff = relu(h @ W1 + b1)
    sgemm_k<2><<<gFF1, blk>>>(h, W1, b1, nullptr, ff, MM, FF, CC);
    // 7. out = x1 + ff @ W2 + b2
    sgemm_k<1><<<gSmall, blk>>>(ff, W2, b2, x1, out, MM, CC, FF);
}

// round 7
// speedup vs baseline: 1.2659x; 1.2659x over previous
#include <cuda_runtime.h>
#include <cuda_bf16.h>
#include <cstdint>

// Problem dims (fixed)
#define BB 4
#define TT 2048
#define CC 1024
#define HH 16
#define DD 64
#define FF 4096
#define MM (BB*TT)   // 8192 rows

// ===================== PTX helpers (sm_100-safe: mma.sync/ldmatrix/cp.async) =
__device__ __forceinline__ uint32_t smem_to_u32(const void* p) {
    uint32_t a;
    asm("{ .reg .u64 t; cvta.to.shared.u64 t, %1; cvt.u32.u64 %0, t; }"
        : "=r"(a) : "l"(p));
    return a;
}
#define CP_ASYNC16(dst, src) \
    asm volatile("cp.async.cg.shared.global [%0], [%1], 16;" :: "r"(dst), "l"(src))
#define CP_COMMIT() asm volatile("cp.async.commit_group;" ::: "memory")
#define CP_WAIT(n)  asm volatile("cp.async.wait_group %0;" :: "n"(n) : "memory")

__device__ __forceinline__ void ldsm4(uint32_t* r, uint32_t addr) {
    asm volatile("ldmatrix.sync.aligned.m8n8.x4.shared.b16 {%0,%1,%2,%3}, [%4];"
        : "=r"(r[0]), "=r"(r[1]), "=r"(r[2]), "=r"(r[3]) : "r"(addr));
}
__device__ __forceinline__ void mma16816(float* c, const uint32_t* a,
                                         uint32_t b0, uint32_t b1) {
    asm volatile(
        "mma.sync.aligned.m16n8k16.row.col.f32.bf16.bf16.f32 "
        "{%0,%1,%2,%3}, {%4,%5,%6,%7}, {%8,%9}, {%0,%1,%2,%3};"
        : "+f"(c[0]), "+f"(c[1]), "+f"(c[2]), "+f"(c[3])
        : "r"(a[0]), "r"(a[1]), "r"(a[2]), "r"(a[3]), "r"(b0), "r"(b1));
}

// ===================== scratch (device globals) =============================
__device__ __nv_bfloat16 g_hh [MM*CC], g_hl [MM*CC];      // LN out hi/lo
__device__ float         g_q  [MM*CC], g_k  [MM*CC], g_v[MM*CC];
__device__ __nv_bfloat16 g_ath[MM*CC], g_atl[MM*CC];      // attention out hi/lo
__device__ float         g_x1 [MM*CC];
__device__ __nv_bfloat16 g_ffh[(size_t)MM*FF], g_ffl[(size_t)MM*FF];
__device__ __nv_bfloat16 g_wqh[CC*CC], g_wql[CC*CC];
__device__ __nv_bfloat16 g_wkh[CC*CC], g_wkl[CC*CC];
__device__ __nv_bfloat16 g_wvh[CC*CC], g_wvl[CC*CC];
__device__ __nv_bfloat16 g_woh[CC*CC], g_wol[CC*CC];
__device__ __nv_bfloat16 g_w1h[(size_t)CC*FF], g_w1l[(size_t)CC*FF];
__device__ __nv_bfloat16 g_w2h[(size_t)FF*CC], g_w2l[(size_t)FF*CC];

// split fp32 -> (hi, lo) bf16 pair, 2 at a time
__device__ __forceinline__ void split2_store(float x0, float x1,
                                             __nv_bfloat16* hp, __nv_bfloat16* lp) {
    __nv_bfloat16 h0 = __float2bfloat16_rn(x0), h1 = __float2bfloat16_rn(x1);
    *(__nv_bfloat162*)hp = __halves2bfloat162(h0, h1);
    float l0 = x0 - __bfloat162float(h0), l1 = x1 - __bfloat162float(h1);
    *(__nv_bfloat162*)lp = __halves2bfloat162(__float2bfloat16_rn(l0),
                                              __float2bfloat16_rn(l1));
}
__device__ __forceinline__ void split4_store(float x0, float x1, float x2, float x3,
                                             __nv_bfloat16* hp, __nv_bfloat16* lp) {
    split2_store(x0, x1, hp, lp);
    split2_store(x2, x3, hp + 2, lp + 2);
}

// ===================== weight transpose + split =============================
// W [K, N] fp32 -> Th/Tl [N, K] bf16 (GEMM B operand is K-major per n-row)
__global__ void __launch_bounds__(256) tsplit_k(const float* __restrict__ W,
                                                __nv_bfloat16* __restrict__ Th,
                                                __nv_bfloat16* __restrict__ Tl,
                                                int K, int N)
{
    __shared__ float t[32][33];
    int n0 = blockIdx.x * 32, k0 = blockIdx.y * 32;
    int tx = threadIdx.x & 31, ty = threadIdx.x >> 5;   // 32 x 8
    #pragma unroll
    for (int i = 0; i < 4; i++)
        t[ty + 8*i][tx] = W[(size_t)(k0 + ty + 8*i) * N + n0 + tx];
    __syncthreads();
    #pragma unroll
    for (int i = 0; i < 4; i++) {
        float v = t[tx][ty + 8*i];
        size_t o = (size_t)(n0 + ty + 8*i) * K + k0 + tx;
        __nv_bfloat16 h = __float2bfloat16_rn(v);
        Th[o] = h;
        Tl[o] = __float2bfloat16_rn(v - __bfloat162float(h));
    }
}

// ===================== LayerNorm -> bf16 hi/lo ==============================
__global__ void __launch_bounds__(256) ln_k(const float* __restrict__ x,
                                            const float* __restrict__ gam,
                                            const float* __restrict__ bet,
                                            __nv_bfloat16* __restrict__ oh,
                                            __nv_bfloat16* __restrict__ ol)
{
    int row = blockIdx.x;
    int tid = threadIdx.x;
    const float4* xr = (const float4*)(x + (size_t)row * CC);
    float4 v = xr[tid];
    float s  = v.x + v.y + v.z + v.w;
    float sq = v.x*v.x + v.y*v.y + v.z*v.z + v.w*v.w;
    #pragma unroll
    for (int o = 16; o > 0; o >>= 1) {
        s  += __shfl_xor_sync(0xffffffffu, s,  o);
        sq += __shfl_xor_sync(0xffffffffu, sq, o);
    }
    __shared__ float rs[8], rq[8];
    int w = tid >> 5, lane = tid & 31;
    if (lane == 0) { rs[w] = s; rq[w] = sq; }
    __syncthreads();
    s = 0.f; sq = 0.f;
    #pragma unroll
    for (int i = 0; i < 8; i++) { s += rs[i]; sq += rq[i]; }
    float mu  = s * (1.f / CC);
    float inv = rsqrtf(sq * (1.f / CC) - mu * mu + 1e-5f);
    float4 g4 = ((const float4*)gam)[tid];
    float4 b4 = ((const float4*)bet)[tid];
    float r0 = (v.x - mu) * inv * g4.x + b4.x;
    float r1 = (v.y - mu) * inv * g4.y + b4.y;
    float r2 = (v.z - mu) * inv * g4.z + b4.z;
    float r3 = (v.w - mu) * inv * g4.w + b4.w;
    size_t base = (size_t)row * CC + tid * 4;
    split4_store(r0, r1, r2, r3, oh + base, ol + base);
}

// ===================== mma.sync GEMM ========================================
// C[M,N] = A[M,K] @ Bt[N,K]^T via 3-term bf16 split (logical K' = 3K):
//   term 0: Ah*Bh, term 1: Al*Bh, term 2: Ah*Bl — fp32 accum.
// 128x128 block, 8 warps (2M x 4N), 64x32 per warp, m16n8k16 frags.
// BK=32 bf16 per stage, cp.async double buffer, smem rows padded to 40 bf16
// (granule 5*row+c mod 8 is a permutation -> conflict-free ldmatrix).
// EP: 0 = fp32 store; 1 = fp32 store of (D+bias+res); 2 = bf16 hi/lo split
//     store of relu(D+bias).
template<int EP>
__global__ void __launch_bounds__(256) gemm_mma(
    const __nv_bfloat16* __restrict__ Ah, const __nv_bfloat16* __restrict__ Al,
    const __nv_bfloat16* __restrict__ Bh, const __nv_bfloat16* __restrict__ Bl,
    const float* __restrict__ bias, const float* __restrict__ res,
    float* __restrict__ Cf,
    __nv_bfloat16* __restrict__ Chi, __nv_bfloat16* __restrict__ Clo,
    int M, int N, int K)
{
    __shared__ __nv_bfloat16 As[2][128][40];
    __shared__ __nv_bfloat16 Bs[2][128][40];

    const int tid  = threadIdx.x;
    const int wid  = tid >> 5;
    const int lane = tid & 31;
    const int bm = blockIdx.y * 128, bn = blockIdx.x * 128;
    const int wm = wid & 1;          // 0..1 -> 64-row slice
    const int wn = wid >> 1;         // 0..3 -> 32-col slice

    const int kc = K >> 5;           // 32-wide chunks per term
    const int kt = 3 * kc;           // total stages

    // loader mapping: thread -> (row = tid/2, 32-byte half-row)
    const int lrow = tid >> 1;
    const int lc   = (tid & 1) * 16;                    // bf16 col offset

    float acc[4][4][4];
    #pragma unroll
    for (int i = 0; i < 4; i++)
        #pragma unroll
        for (int j = 0; j < 4; j++)
            #pragma unroll
            for (int q = 0; q < 4; q++) acc[i][j][q] = 0.f;

    // ---- stage issue helper (inlined manually via lambda) ----
    auto issue = [&](int t, int buf) {
        int term = (t >= 2*kc) ? 2 : (t >= kc ? 1 : 0);
        int koff = (t - term * kc) * 32;
        const __nv_bfloat16* pa = (term == 1) ? Al : Ah;
        const __nv_bfloat16* pb = (term == 2) ? Bl : Bh;
        const __nv_bfloat16* ga = pa + (size_t)(bm + lrow) * K + koff + lc;
        const __nv_bfloat16* gb = pb + (size_t)(bn + lrow) * K + koff + lc;
        uint32_t da = smem_to_u32(&As[buf][lrow][lc]);
        uint32_t db = smem_to_u32(&Bs[buf][lrow][lc]);
        CP_ASYNC16(da,      ga);
        CP_ASYNC16(da + 16, ga + 8);
        CP_ASYNC16(db,      gb);
        CP_ASYNC16(db + 16, gb + 8);
    };

    issue(0, 0);
    CP_COMMIT();

    for (int t = 0; t < kt; t++) {
        const int buf = t & 1;
        if (t + 1 < kt) {
            issue(t + 1, buf ^ 1);
            CP_COMMIT();
            CP_WAIT(1);
        } else {
            CP_WAIT(0);
        }
        __syncthreads();

        // ---- compute stage: 2 k-steps of 16 ----
        #pragma unroll
        for (int ks = 0; ks < 2; ks++) {
            const int kb = ks * 16 + (lane >> 4) * 8;   // ldmatrix col
            uint32_t a[4][4];
            #pragma unroll
            for (int mf = 0; mf < 4; mf++) {
                uint32_t addr = smem_to_u32(&As[buf][wm*64 + mf*16 + (lane & 15)][kb]);
                ldsm4(a[mf], addr);
            }
            uint32_t b[2][4];
            #pragma unroll
            for (int bf = 0; bf < 2; bf++) {
                uint32_t addr = smem_to_u32(&Bs[buf][wn*32 + bf*16 + (lane & 15)][kb]);
                ldsm4(b[bf], addr);
            }
            #pragma unroll
            for (int mf = 0; mf < 4; mf++) {
                #pragma unroll
                for (int nf = 0; nf < 4; nf++) {
                    uint32_t b0 = b[nf >> 1][(nf & 1) ? 1 : 0];
                    uint32_t b1 = b[nf >> 1][(nf & 1) ? 3 : 2];
                    mma16816(acc[mf][nf], a[mf], b0, b1);
                }
            }
        }
        __syncthreads();
    }

    // ---- epilogue ----
    const int r0 = bm + wm * 64 + (lane >> 2);
    const int c0 = bn + wn * 32 + (lane & 3) * 2;
    #pragma unroll
    for (int mf = 0; mf < 4; mf++) {
        #pragma unroll
        for (int nf = 0; nf < 4; nf++) {
            int row = r0 + mf * 16;
            int col = c0 + nf * 8;
            #pragma unroll
            for (int half = 0; half < 2; half++) {       // rows row, row+8
                int rr = row + half * 8;
                float v0 = acc[mf][nf][half*2 + 0];
                float v1 = acc[mf][nf][half*2 + 1];
                size_t o = (size_t)rr * N + col;
                if (EP >= 1) {
                    float2 bb = *(const float2*)(bias + col);
                    v0 += bb.x; v1 += bb.y;
                }
                if (EP == 2) {
                    v0 = fmaxf(v0, 0.f); v1 = fmaxf(v1, 0.f);
                    split2_store(v0, v1, Chi + o, Clo + o);
                } else {
                    if (EP == 1) {
                        float2 rv = *(const float2*)(res + o);
                        v0 += rv.x; v1 += rv.y;
                    }
                    *(float2*)(Cf + o) = make_float2(v0, v1);
                }
            }
        }
    }
}

// ===================== Flash attention (causal, fp32 -> bf16 hi/lo out) =====
__global__ void __launch_bounds__(128) flash_k(const float* __restrict__ Q,
                                               const float* __restrict__ Kg,
                                               const float* __restrict__ Vg,
                                               __nv_bfloat16* __restrict__ Oh,
                                               __nv_bfloat16* __restrict__ Ol)
{
    __shared__ float q_s[128][68];
    __shared__ float k_s[16][64];
    __shared__ float v_s[16][64];
    int qt  = blockIdx.x;
    int bh  = blockIdx.y;
    int b   = bh >> 4, h = bh & 15;
    int tid = threadIdx.x;

    const float* Qb  = Q  + ((size_t)(b * TT + qt * 128)) * CC + h * DD;
    const float* Kb0 = Kg + ((size_t)b * TT) * CC + h * DD;
    const float* Vb0 = Vg + ((size_t)b * TT) * CC + h * DD;

    for (int idx = tid; idx < 128 * 16; idx += 128) {
        int r = idx >> 4, d4 = idx & 15;
        float4 t = *(const float4*)(Qb + (size_t)r * CC + d4 * 4);
        t.x *= 0.03125f; t.y *= 0.03125f; t.z *= 0.03125f; t.w *= 0.03125f;
        *(float4*)&q_s[r][d4 * 4] = t;
    }

    int qrow = qt * 128 + tid;
    float m = -1e30f, l = 0.f;
    float o[64];
    #pragma unroll
    for (int d = 0; d < 64; d++) o[d] = 0.f;

    int kend = qt * 128 + 128;
    for (int k0 = 0; k0 < kend; k0 += 16) {
        __syncthreads();
        for (int idx = tid; idx < 16 * 16; idx += 128) {
            int r = idx >> 4, d4 = idx & 15;
            *(float4*)&k_s[r][d4*4] = *(const float4*)(Kb0 + (size_t)(k0 + r) * CC + d4 * 4);
            *(float4*)&v_s[r][d4*4] = *(const float4*)(Vb0 + (size_t)(k0 + r) * CC + d4 * 4);
        }
        __syncthreads();

        float s[16];
        #pragma unroll
        for (int j = 0; j < 16; j++) s[j] = 0.f;
        #pragma unroll 4
        for (int d4 = 0; d4 < 16; d4++) {
            float4 q4 = *(const float4*)&q_s[tid][d4 * 4];
            #pragma unroll
            for (int j = 0; j < 16; j++) {
                float4 k4 = *(const float4*)&k_s[j][d4 * 4];
                s[j] += q4.x*k4.x + q4.y*k4.y + q4.z*k4.z + q4.w*k4.w;
            }
        }
        if (k0 + 15 > qrow) {
            #pragma unroll
            for (int j = 0; j < 16; j++)
                if (k0 + j > qrow) s[j] = -1e30f;
        }
        float mt = m;
        #pragma unroll
        for (int j = 0; j < 16; j++) mt = fmaxf(mt, s[j]);
        float alpha = __expf(m - mt);
        m = mt;
        l *= alpha;
        #pragma unroll
        for (int d = 0; d < 64; d++) o[d] *= alpha;
        #pragma unroll 4
        for (int j = 0; j < 16; j++) {
            float p = __expf(s[j] - m);
            l += p;
            #pragma unroll
            for (int d4 = 0; d4 < 16; d4++) {
                float4 v4 = *(const float4*)&v_s[j][d4 * 4];
                o[d4*4+0] += p * v4.x;
                o[d4*4+1] += p * v4.y;
                o[d4*4+2] += p * v4.z;
                o[d4*4+3] += p * v4.w;
            }
        }
    }
    float inv = 1.f / l;
    size_t base = ((size_t)(b * TT + qrow)) * CC + h * DD;
    #pragma unroll
    for (int d4 = 0; d4 < 16; d4++) {
        split4_store(o[d4*4+0]*inv, o[d4*4+1]*inv, o[d4*4+2]*inv, o[d4*4+3]*inv,
                     Oh + base + d4*4, Ol + base + d4*4);
    }
}

// ===================== launch ===============================================
extern "C" void kernel_launch(void* const* d_in, const int* in_sizes, int n_in,
                              void* d_out, int out_size)
{
    const float* x     = (const float*)d_in[0];
    const float* Wq    = (const float*)d_in[1];
    const float* Wk    = (const float*)d_in[2];
    const float* Wv    = (const float*)d_in[3];
    const float* Wo    = (const float*)d_in[4];
    const float* bo    = (const float*)d_in[5];
    const float* W1    = (const float*)d_in[6];
    const float* b1    = (const float*)d_in[7];
    const float* W2    = (const float*)d_in[8];
    const float* b2    = (const float*)d_in[9];
    const float* ln1g  = (const float*)d_in[10];
    const float* ln1b  = (const float*)d_in[11];
    const float* ln2g  = (const float*)d_in[12];
    const float* ln2b  = (const float*)d_in[13];
    float* out = (float*)d_out;

    __nv_bfloat16 *hh, *hl, *ath, *atl, *ffh, *ffl;
    __nv_bfloat16 *wqh, *wql, *wkh, *wkl, *wvh, *wvl, *woh, *wol, *w1h, *w1l, *w2h, *w2l;
    float *q, *k, *v, *x1;
    cudaGetSymbolAddress((void**)&hh,  g_hh);  cudaGetSymbolAddress((void**)&hl,  g_hl);
    cudaGetSymbolAddress((void**)&q,   g_q);   cudaGetSymbolAddress((void**)&k,   g_k);
    cudaGetSymbolAddress((void**)&v,   g_v);
    cudaGetSymbolAddress((void**)&ath, g_ath); cudaGetSymbolAddress((void**)&atl, g_atl);
    cudaGetSymbolAddress((void**)&x1,  g_x1);
    cudaGetSymbolAddress((void**)&ffh, g_ffh); cudaGetSymbolAddress((void**)&ffl, g_ffl);
    cudaGetSymbolAddress((void**)&wqh, g_wqh); cudaGetSymbolAddress((void**)&wql, g_wql);
    cudaGetSymbolAddress((void**)&wkh, g_wkh); cudaGetSymbolAddress((void**)&wkl, g_wkl);
    cudaGetSymbolAddress((void**)&wvh, g_wvh); cudaGetSymbolAddress((void**)&wvl, g_wvl);
    cudaGetSymbolAddress((void**)&woh, g_woh); cudaGetSymbolAddress((void**)&wol, g_wol);
    cudaGetSymbolAddress((void**)&w1h, g_w1h); cudaGetSymbolAddress((void**)&w1l, g_w1l);
    cudaGetSymbolAddress((void**)&w2h, g_w2h); cudaGetSymbolAddress((void**)&w2l, g_w2l);

    dim3 t256(256);
    dim3 tsq(CC/32, CC/32);

    // weight transpose+split (Wt[N][K] bf16 hi/lo)
    tsplit_k<<<tsq, t256>>>(Wq, wqh, wql, CC, CC);
    tsplit_k<<<tsq, t256>>>(Wk, wkh, wkl, CC, CC);
    tsplit_k<<<tsq, t256>>>(Wv, wvh, wvl, CC, CC);
    tsplit_k<<<tsq, t256>>>(Wo, woh, wol, CC, CC);
    tsplit_k<<<dim3(FF/32, CC/32), t256>>>(W1, w1h, w1l, CC, FF);
    tsplit_k<<<dim3(CC/32, FF/32), t256>>>(W2, w2h, w2l, FF, CC);

    dim3 gSmall(CC/128, MM/128);   // (8, 64)
    dim3 gFF1  (FF/128, MM/128);   // (32, 64)

    // 1. h = LN1(x) -> bf16 hi/lo
    ln_k<<<MM, 256>>>(x, ln1g, ln1b, hh, hl);
    // 2. q,k,v = h @ W{q,k,v}  (fp32 out for attention)
    gemm_mma<0><<<gSmall, t256>>>(hh, hl, wqh, wql, nullptr, nullptr, q, nullptr, nullptr, MM, CC, CC);
    gemm_mma<0><<<gSmall, t256>>>(hh, hl, wkh, wkl, nullptr, nullptr, k, nullptr, nullptr, MM, CC, CC);
    gemm_mma<0><<<gSmall, t256>>>(hh, hl, wvh, wvl, nullptr, nullptr, v, nullptr, nullptr, MM, CC, CC);
    // 3. attention -> bf16 hi/lo
    flash_k<<<dim3(TT/128, BB*HH), 128>>>(q, k, v, ath, atl);
    // 4. x1 = x + at @ Wo + bo (fp32)
    gemm_mma<1><<<gSmall, t256>>>(ath, atl, woh, wol, bo, x, x1, nullptr, nullptr, MM, CC, CC);
    // 5. h = LN2(x1) -> bf16 hi/lo
    ln_k<<<MM, 256>>>(x1, ln2g, ln2b, hh, hl);
    // 6. ff = relu(h @ W1 + b1) -> bf16 hi/lo
    gemm_mma<2><<<gFF1, t256>>>(hh, hl, w1h, w1l, b1, nullptr, nullptr, ffh, ffl, MM, FF, CC);
    // 7. out = x1 + ff @ W2 + b2 (fp32)
    gemm_mma<1><<<gSmall, t256>>>(ffh, ffl, w2h, w2l, b2, x1, out, nullptr, nullptr, MM, CC, FF);
}